// round 2
// baseline (speedup 1.0000x reference)
#include <cuda_runtime.h>
#include <math_constants.h>

#define MDIM 5184        // 72*72
#define CDIM 256
#define BM   128
#define BN   128
#define BK   16
#define NBLK ((MDIM + BM - 1) / BM)   // 41 (last block row/col partially out of range)
#define OUT_H 224
#define OUT_W 224

// Scratch (allocation-free): fused reduction targets.
__device__ float        g_rpos[MDIM];   // row sums of relu(d)
__device__ float        g_rneg[MDIM];   // row sums of relu(-d)
__device__ float        g_cpos[MDIM];   // col sums of relu(d)
__device__ float        g_cneg[MDIM];   // col sums of relu(-d)
__device__ unsigned int g_maxkey;       // monotone-uint-encoded global max

// Monotone float->uint key: preserves ordering for atomicMax over any-sign floats.
__device__ __forceinline__ unsigned int fkey(float f) {
    unsigned int u = __float_as_uint(f);
    return (u & 0x80000000u) ? ~u : (u | 0x80000000u);
}

__global__ void simcam_init() {
    int i = blockIdx.x * blockDim.x + threadIdx.x;
    if (i < MDIM) { g_rpos[i] = 0.f; g_rneg[i] = 0.f; g_cpos[i] = 0.f; g_cneg[i] = 0.f; }
    if (i == 0) g_maxkey = 0u;
}

// Fused GEMM (A·B^T, A=x[0], B=x[1], both [5184,256] row-major) + relu row/col sums + global max.
__global__ __launch_bounds__(256) void simcam_gemm(const float* __restrict__ x) {
    const float* __restrict__ A = x;
    const float* __restrict__ B = x + (size_t)MDIM * CDIM;

    __shared__ float As[BK][BM + 4];   // +4 pad: cuts transposed-store bank conflicts to 2-way
    __shared__ float Bs[BK][BN + 4];
    __shared__ float s_rp[BM], s_rn[BM], s_cp[BN], s_cn[BN];
    __shared__ float s_wmax[8];

    const int bm  = blockIdx.y * BM;
    const int bn  = blockIdx.x * BN;
    const int tid = threadIdx.x;
    const int tx  = tid & 15;          // 16x16 thread grid, 8x8 microtile each
    const int ty  = tid >> 4;

    if (tid < BM) { s_rp[tid] = 0.f; s_rn[tid] = 0.f; s_cp[tid] = 0.f; s_cn[tid] = 0.f; }

    float acc[8][8];
    #pragma unroll
    for (int i = 0; i < 8; i++)
        #pragma unroll
        for (int j = 0; j < 8; j++) acc[i][j] = 0.f;

    for (int k0 = 0; k0 < CDIM; k0 += BK) {
        // Load 128x16 tiles of A and B (transposed into smem). 512 float4 per tile,
        // 256 threads -> 2 each. Out-of-range rows clamp to last row (excluded later).
        #pragma unroll
        for (int l = 0; l < 2; l++) {
            int idx = tid + l * 256;
            int r   = idx >> 2;
            int kq  = (idx & 3) << 2;
            int gr  = bm + r; gr = gr < MDIM ? gr : MDIM - 1;
            float4 va = *(const float4*)(A + (size_t)gr * CDIM + k0 + kq);
            As[kq + 0][r] = va.x; As[kq + 1][r] = va.y;
            As[kq + 2][r] = va.z; As[kq + 3][r] = va.w;
            int gc  = bn + r; gc = gc < MDIM ? gc : MDIM - 1;
            float4 vb = *(const float4*)(B + (size_t)gc * CDIM + k0 + kq);
            Bs[kq + 0][r] = vb.x; Bs[kq + 1][r] = vb.y;
            Bs[kq + 2][r] = vb.z; Bs[kq + 3][r] = vb.w;
        }
        __syncthreads();

        #pragma unroll
        for (int kk = 0; kk < BK; kk++) {
            float ra[8], rb[8];
            #pragma unroll
            for (int i = 0; i < 8; i++) ra[i] = As[kk][ty * 8 + i];
            #pragma unroll
            for (int j = 0; j < 8; j++) rb[j] = Bs[kk][tx * 8 + j];
            #pragma unroll
            for (int i = 0; i < 8; i++)
                #pragma unroll
                for (int j = 0; j < 8; j++)
                    acc[i][j] = fmaf(ra[i], rb[j], acc[i][j]);
        }
        __syncthreads();
    }

    // ---- Fused epilogue: relu row/col partial sums + max (valid indices only) ----
    float tmax = -CUDART_INF_F;
    float cp[8], cn[8];
    #pragma unroll
    for (int j = 0; j < 8; j++) { cp[j] = 0.f; cn[j] = 0.f; }

    #pragma unroll
    for (int i = 0; i < 8; i++) {
        int  gr = bm + ty * 8 + i;
        bool rv = gr < MDIM;
        float rp = 0.f, rn = 0.f;
        #pragma unroll
        for (int j = 0; j < 8; j++) {
            int gc = bn + tx * 8 + j;
            if (rv && gc < MDIM) {
                float v = acc[i][j];
                float p = fmaxf(v, 0.f);
                float n = fmaxf(-v, 0.f);
                rp += p; rn += n;
                cp[j] += p; cn[j] += n;
                tmax = fmaxf(tmax, v);
            }
        }
        if (rv) { atomicAdd(&s_rp[ty * 8 + i], rp); atomicAdd(&s_rn[ty * 8 + i], rn); }
    }
    #pragma unroll
    for (int j = 0; j < 8; j++) {
        if (bn + tx * 8 + j < MDIM) {
            atomicAdd(&s_cp[tx * 8 + j], cp[j]);
            atomicAdd(&s_cn[tx * 8 + j], cn[j]);
        }
    }

    // Block max reduce
    #pragma unroll
    for (int off = 16; off; off >>= 1)
        tmax = fmaxf(tmax, __shfl_xor_sync(0xffffffffu, tmax, off));
    if ((tid & 31) == 0) s_wmax[tid >> 5] = tmax;
    __syncthreads();
    if (tid == 0) {
        float bmax = s_wmax[0];
        #pragma unroll
        for (int w = 1; w < 8; w++) bmax = fmaxf(bmax, s_wmax[w]);
        atomicMax(&g_maxkey, fkey(bmax));
    }

    // Flush block-level sums to global (one atomic per row/col per block)
    if (tid < BM) {
        int gr = bm + tid;
        if (gr < MDIM) { atomicAdd(&g_rpos[gr], s_rp[tid]); atomicAdd(&g_rneg[gr], s_rn[tid]); }
        int gc = bn + tid;
        if (gc < MDIM) { atomicAdd(&g_cpos[gc], s_cp[tid]); atomicAdd(&g_cneg[gc], s_cn[tid]); }
    }
}

// Bilinear resize (align_corners=False) of the two 72x72 maps to 2x224x224,
// with the deferred 1/|M| scale and pos/neg selection by sign(M).
__global__ void simcam_resize(float* __restrict__ out, int total) {
    int idx = blockIdx.x * blockDim.x + threadIdx.x;
    if (idx >= total) return;
    int p   = idx / (OUT_H * OUT_W);
    int rem = idx % (OUT_H * OUT_W);
    int oy  = rem / OUT_W;
    int ox  = rem % OUT_W;

    unsigned int key = g_maxkey;
    float Mv = (key & 0x80000000u) ? __uint_as_float(key & 0x7fffffffu)
                                   : __uint_as_float(~key);
    const float* src;
    float inv;
    if (Mv > 0.f)      { src = (p == 0) ? g_rpos : g_cpos; inv =  1.0f / Mv; }
    else if (Mv < 0.f) { src = (p == 0) ? g_rneg : g_cneg; inv = -1.0f / Mv; }
    else               { src = (p == 0) ? g_rpos : g_cpos; inv = 0.0f; }

    const float s = 72.0f / 224.0f;
    float ys = fmaxf(((float)oy + 0.5f) * s - 0.5f, 0.0f);
    float xs = fmaxf(((float)ox + 0.5f) * s - 0.5f, 0.0f);
    int y0 = (int)floorf(ys), x0 = (int)floorf(xs);
    int y1 = min(y0 + 1, 71), x1 = min(x0 + 1, 71);
    float wy = ys - (float)y0, wx = xs - (float)x0;

    float a = src[y0 * 72 + x0], b = src[y0 * 72 + x1];
    float c = src[y1 * 72 + x0], d = src[y1 * 72 + x1];
    float v = a * (1.f - wy) * (1.f - wx) + b * (1.f - wy) * wx
            + c * wy * (1.f - wx)         + d * wy * wx;
    out[idx] = v * inv;
}

extern "C" void kernel_launch(void* const* d_in, const int* in_sizes, int n_in,
                              void* d_out, int out_size) {
    const float* x = (const float*)d_in[0];   // (2,72,72,256) fp32; H,W inputs unused (fixed 224)
    simcam_init<<<(MDIM + 255) / 256, 256>>>();
    dim3 grid(NBLK, NBLK);
    simcam_gemm<<<grid, 256>>>(x);
    simcam_resize<<<(out_size + 255) / 256, 256>>>((float*)d_out, out_size);
}

// round 4
// speedup vs baseline: 2.4960x; 2.4960x over previous
#include <cuda_runtime.h>
#include <cuda_bf16.h>
#include <math_constants.h>
#include <cstdint>

// ---------------- Geometry ----------------
#define MDIM  5184          // 72*72
#define CDIM  256
#define MPAD  5248          // 41 * 128
#define NBLK  41
#define NK    8             // K chunks of 32 over CDIM
#define OUT_H 224
#define OUT_W 224

// smem stage: 4 operand tiles (Ah, Al, Bh, Bl), each 128 rows x 32 bf16, row stride 80 B
#define ROW_STRIDE 80
#define OP_BYTES   (128 * ROW_STRIDE)          // 10240
#define OFF_AH     0
#define OFF_AL     (1 * OP_BYTES)
#define OFF_BH     (2 * OP_BYTES)
#define OFF_BL     (3 * OP_BYTES)
#define STAGE      (4 * OP_BYTES)              // 40960
#define DYN_SMEM   (2 * STAGE)                 // 81920

// ---------------- Device scratch (allocation-free) ----------------
// Row-major [MPAD][512] bf16: cols [0,256)=hi, [256,512)=lo. 5.4 MB each.
__device__ __align__(16) __nv_bfloat16 g_A2[MPAD * 512];
__device__ __align__(16) __nv_bfloat16 g_B2[MPAD * 512];
__device__ float        g_rpos[MDIM], g_rneg[MDIM], g_cpos[MDIM], g_cneg[MDIM];
__device__ unsigned int g_maxkey;

// ---------------- PTX helpers (baseline sm_100: cp.async / ldmatrix / HMMA) ----------------
__device__ __forceinline__ uint32_t smem_u32(const void* p) {
    uint32_t a;
    asm("{ .reg .u64 t; cvta.to.shared.u64 t, %1; cvt.u32.u64 %0, t; }" : "=r"(a) : "l"(p));
    return a;
}
__device__ __forceinline__ unsigned int fkey(float f) {
    unsigned int u = __float_as_uint(f);
    return (u & 0x80000000u) ? ~u : (u | 0x80000000u);
}

#define CP16(dst, src) \
    asm volatile("cp.async.cg.shared.global [%0], [%1], 16;" :: "r"(dst), "l"(src))
#define CP_COMMIT()  asm volatile("cp.async.commit_group;")
#define CP_WAIT1()   asm volatile("cp.async.wait_group 1;")
#define CP_WAIT0()   asm volatile("cp.async.wait_group 0;")

#define LDSM4(r0, r1, r2, r3, a) \
    asm volatile("ldmatrix.sync.aligned.m8n8.x4.shared.b16 {%0,%1,%2,%3}, [%4];" \
                 : "=r"(r0), "=r"(r1), "=r"(r2), "=r"(r3) : "r"(a))

#define MMA16816(d, a, b) \
    asm volatile("mma.sync.aligned.m16n8k16.row.col.f32.bf16.bf16.f32 " \
                 "{%0,%1,%2,%3}, {%4,%5,%6,%7}, {%8,%9}, {%0,%1,%2,%3};" \
                 : "+f"((d)[0]), "+f"((d)[1]), "+f"((d)[2]), "+f"((d)[3]) \
                 : "r"((a)[0]), "r"((a)[1]), "r"((a)[2]), "r"((a)[3]), \
                   "r"((b)[0]), "r"((b)[1]))

// ---------------- Kernels ----------------

// Zero reduction arrays + pad rows [5184,5248) of both bf16 operand arrays.
__global__ void simcam_init() {
    int i = blockIdx.x * blockDim.x + threadIdx.x;
    if (i < MDIM) { g_rpos[i] = 0.f; g_rneg[i] = 0.f; g_cpos[i] = 0.f; g_cneg[i] = 0.f; }
    if (i == 0) g_maxkey = 0u;
    // pad: 64 rows * 1024 B = 4096 uint4 per array
    if (i < 8192) {
        const uint4 z = make_uint4(0u, 0u, 0u, 0u);
        __nv_bfloat16* base = (i < 4096) ? g_A2 : g_B2;
        int u = i & 4095;
        ((uint4*)(base + (size_t)MDIM * 512))[u] = z;
    }
}

// fp32 -> bf16 hi/lo split: row r of x[op] -> g_?2[r][k]=hi, g_?2[r][256+k]=lo.
__global__ void simcam_conv(const float* __restrict__ x) {
    int id = blockIdx.x * blockDim.x + threadIdx.x;
    if (id >= 2 * MDIM * 128) return;
    int op  = id >= MDIM * 128;
    int rid = op ? id - MDIM * 128 : id;
    int r   = rid >> 7;
    int k0  = (rid & 127) * 2;
    float2 v = *(const float2*)(x + ((size_t)op * MDIM + r) * CDIM + k0);
    __nv_bfloat16 h0 = __float2bfloat16(v.x);
    __nv_bfloat16 h1 = __float2bfloat16(v.y);
    __nv_bfloat16 l0 = __float2bfloat16(v.x - __bfloat162float(h0));
    __nv_bfloat16 l1 = __float2bfloat16(v.y - __bfloat162float(h1));
    unsigned int hpack = ((unsigned)__bfloat16_as_ushort(h1) << 16) | __bfloat16_as_ushort(h0);
    unsigned int lpack = ((unsigned)__bfloat16_as_ushort(l1) << 16) | __bfloat16_as_ushort(l0);
    __nv_bfloat16* base = op ? g_B2 : g_A2;
    *(unsigned int*)(base + (size_t)r * 512 + k0)       = hpack;
    *(unsigned int*)(base + (size_t)r * 512 + 256 + k0) = lpack;
}

__device__ __forceinline__ void load_stage(uint32_t sb, const unsigned char* Asrc,
                                           const unsigned char* Bsrc, int kc, int tid) {
    #pragma unroll
    for (int i = 0; i < 2; i++) {
        int idx = tid + i * 256;           // 0..511
        int row = idx >> 2;
        int ch  = idx & 3;
        uint32_t soff = (uint32_t)(row * ROW_STRIDE + ch * 16);
        size_t   goff = (size_t)row * 1024 + kc * 64 + ch * 16;
        CP16(sb + OFF_AH + soff, Asrc + goff);
        CP16(sb + OFF_AL + soff, Asrc + goff + 512);
        CP16(sb + OFF_BH + soff, Bsrc + goff);
        CP16(sb + OFF_BL + soff, Bsrc + goff + 512);
    }
}

// Fused GEMM: C = Ah*Bh^T + Al*Bh^T + Ah*Bl^T, 128x128 CTA tile, + relu row/col sums + max.
__global__ __launch_bounds__(256, 2) void simcam_gemm() {
    extern __shared__ unsigned char dsm[];
    __shared__ float s_rp[128], s_rn[128], s_cp[128], s_cn[128], s_wmax[8];

    const int tid  = threadIdx.x;
    const int wid  = tid >> 5, lane = tid & 31;
    const int wm   = wid & 3, wn = wid >> 2;     // 4x2 warp grid; warp tile 32(M) x 64(N)
    const int bm   = blockIdx.y, bn = blockIdx.x;

    if (tid < 128) { s_rp[tid] = 0.f; s_rn[tid] = 0.f; s_cp[tid] = 0.f; s_cn[tid] = 0.f; }

    const unsigned char* Asrc = (const unsigned char*)(g_A2 + (size_t)bm * 128 * 512);
    const unsigned char* Bsrc = (const unsigned char*)(g_B2 + (size_t)bn * 128 * 512);
    const uint32_t dyn = smem_u32(dsm);

    // ldmatrix per-lane address components (4 mats: rows(l&15), chunk(l>>4))
    const uint32_t a_off = (uint32_t)((wm * 32 + (lane & 15)) * ROW_STRIDE + (lane >> 4) * 16);
    const uint32_t b_off = (uint32_t)((wn * 64 + (lane & 15)) * ROW_STRIDE + (lane >> 4) * 16);

    float acc[2][8][4];
    #pragma unroll
    for (int mi = 0; mi < 2; mi++)
        #pragma unroll
        for (int nf = 0; nf < 8; nf++)
            #pragma unroll
            for (int r = 0; r < 4; r++) acc[mi][nf][r] = 0.f;

    load_stage(dyn, Asrc, Bsrc, 0, tid);
    CP_COMMIT();

    for (int kc = 0; kc < NK; kc++) {
        if (kc + 1 < NK) {
            load_stage(dyn + ((kc + 1) & 1) * STAGE, Asrc, Bsrc, kc + 1, tid);
            CP_COMMIT();
            CP_WAIT1();
        } else {
            CP_WAIT0();
        }
        __syncthreads();

        const uint32_t base = dyn + (kc & 1) * STAGE;
        #pragma unroll
        for (int s = 0; s < 2; s++) {
            uint32_t ah[2][4], al[2][4], bb[8][2];
            // A-hi fragments (2 x m16k16)
            #pragma unroll
            for (int mi = 0; mi < 2; mi++)
                LDSM4(ah[mi][0], ah[mi][1], ah[mi][2], ah[mi][3],
                      base + OFF_AH + a_off + mi * (16 * ROW_STRIDE) + s * 32);
            // B-hi fragments (8 x n8k16)
            #pragma unroll
            for (int g = 0; g < 4; g++) {
                uint32_t r0, r1, r2, r3;
                LDSM4(r0, r1, r2, r3, base + OFF_BH + b_off + g * (16 * ROW_STRIDE) + s * 32);
                bb[2 * g][0] = r0; bb[2 * g][1] = r2;
                bb[2 * g + 1][0] = r1; bb[2 * g + 1][1] = r3;
            }
            #pragma unroll
            for (int mi = 0; mi < 2; mi++)
                #pragma unroll
                for (int nf = 0; nf < 8; nf++) MMA16816(acc[mi][nf], ah[mi], bb[nf]);
            // A-lo * B-hi
            #pragma unroll
            for (int mi = 0; mi < 2; mi++)
                LDSM4(al[mi][0], al[mi][1], al[mi][2], al[mi][3],
                      base + OFF_AL + a_off + mi * (16 * ROW_STRIDE) + s * 32);
            #pragma unroll
            for (int mi = 0; mi < 2; mi++)
                #pragma unroll
                for (int nf = 0; nf < 8; nf++) MMA16816(acc[mi][nf], al[mi], bb[nf]);
            // A-hi * B-lo (overwrite B regs)
            #pragma unroll
            for (int g = 0; g < 4; g++) {
                uint32_t r0, r1, r2, r3;
                LDSM4(r0, r1, r2, r3, base + OFF_BL + b_off + g * (16 * ROW_STRIDE) + s * 32);
                bb[2 * g][0] = r0; bb[2 * g][1] = r2;
                bb[2 * g + 1][0] = r1; bb[2 * g + 1][1] = r3;
            }
            #pragma unroll
            for (int mi = 0; mi < 2; mi++)
                #pragma unroll
                for (int nf = 0; nf < 8; nf++) MMA16816(acc[mi][nf], ah[mi], bb[nf]);
        }
        __syncthreads();
    }

    // ---- Fused epilogue ----
    // Fragment mapping: rows = wm*32 + mi*16 + (lane>>2) + {0,8}; cols = wn*64 + nf*8 + (lane&3)*2 + {0,1}
    float tmax = -CUDART_INF_F;
    const int rbase = bm * 128 + wm * 32;
    const int cbase = bn * 128 + wn * 64;

    #pragma unroll
    for (int mi = 0; mi < 2; mi++) {
        #pragma unroll
        for (int h = 0; h < 2; h++) {
            float rp = 0.f, rn = 0.f;
            #pragma unroll
            for (int nf = 0; nf < 8; nf++) {
                float v0 = acc[mi][nf][2 * h], v1 = acc[mi][nf][2 * h + 1];
                rp += fmaxf(v0, 0.f) + fmaxf(v1, 0.f);
                rn += fmaxf(-v0, 0.f) + fmaxf(-v1, 0.f);
                int grow = rbase + mi * 16 + (lane >> 2) + h * 8;
                int gc0  = cbase + nf * 8 + (lane & 3) * 2;
                if (grow < MDIM && gc0 < MDIM)     tmax = fmaxf(tmax, v0);
                if (grow < MDIM && gc0 + 1 < MDIM) tmax = fmaxf(tmax, v1);
            }
            rp += __shfl_xor_sync(0xffffffffu, rp, 1); rp += __shfl_xor_sync(0xffffffffu, rp, 2);
            rn += __shfl_xor_sync(0xffffffffu, rn, 1); rn += __shfl_xor_sync(0xffffffffu, rn, 2);
            if ((lane & 3) == 0) {
                int r = wm * 32 + mi * 16 + (lane >> 2) + h * 8;
                atomicAdd(&s_rp[r], rp);
                atomicAdd(&s_rn[r], rn);
            }
        }
    }
    #pragma unroll
    for (int nf = 0; nf < 8; nf++) {
        #pragma unroll
        for (int j = 0; j < 2; j++) {
            float cp = 0.f, cn = 0.f;
            #pragma unroll
            for (int mi = 0; mi < 2; mi++) {
                float v0 = acc[mi][nf][j], v1 = acc[mi][nf][j + 2];
                cp += fmaxf(v0, 0.f) + fmaxf(v1, 0.f);
                cn += fmaxf(-v0, 0.f) + fmaxf(-v1, 0.f);
            }
            cp += __shfl_xor_sync(0xffffffffu, cp, 4);
            cp += __shfl_xor_sync(0xffffffffu, cp, 8);
            cp += __shfl_xor_sync(0xffffffffu, cp, 16);
            cn += __shfl_xor_sync(0xffffffffu, cn, 4);
            cn += __shfl_xor_sync(0xffffffffu, cn, 8);
            cn += __shfl_xor_sync(0xffffffffu, cn, 16);
            if (lane < 4) {
                int c = wn * 64 + nf * 8 + lane * 2 + j;
                atomicAdd(&s_cp[c], cp);
                atomicAdd(&s_cn[c], cn);
            }
        }
    }
    #pragma unroll
    for (int off = 16; off; off >>= 1)
        tmax = fmaxf(tmax, __shfl_xor_sync(0xffffffffu, tmax, off));
    if (lane == 0) s_wmax[wid] = tmax;
    __syncthreads();

    if (tid < 128) {
        int gr = bm * 128 + tid;
        if (gr < MDIM) { atomicAdd(&g_rpos[gr], s_rp[tid]); atomicAdd(&g_rneg[gr], s_rn[tid]); }
        int gc = bn * 128 + tid;
        if (gc < MDIM) { atomicAdd(&g_cpos[gc], s_cp[tid]); atomicAdd(&g_cneg[gc], s_cn[tid]); }
    }
    if (tid == 0) {
        float bmax = s_wmax[0];
        #pragma unroll
        for (int w = 1; w < 8; w++) bmax = fmaxf(bmax, s_wmax[w]);
        atomicMax(&g_maxkey, fkey(bmax));
    }
}

// Bilinear resize (align_corners=False) with deferred 1/|M| scale + pos/neg selection.
__global__ void simcam_resize(float* __restrict__ out, int total) {
    int idx = blockIdx.x * blockDim.x + threadIdx.x;
    if (idx >= total) return;
    int p   = idx / (OUT_H * OUT_W);
    int rem = idx % (OUT_H * OUT_W);
    int oy  = rem / OUT_W;
    int ox  = rem % OUT_W;

    unsigned int key = g_maxkey;
    float Mv = (key & 0x80000000u) ? __uint_as_float(key & 0x7fffffffu)
                                   : __uint_as_float(~key);
    const float* src;
    float inv;
    if (Mv > 0.f)      { src = (p == 0) ? g_rpos : g_cpos; inv =  1.0f / Mv; }
    else if (Mv < 0.f) { src = (p == 0) ? g_rneg : g_cneg; inv = -1.0f / Mv; }
    else               { src = (p == 0) ? g_rpos : g_cpos; inv = 0.0f; }

    const float s = 72.0f / 224.0f;
    float ys = fmaxf(((float)oy + 0.5f) * s - 0.5f, 0.0f);
    float xs = fmaxf(((float)ox + 0.5f) * s - 0.5f, 0.0f);
    int y0 = (int)floorf(ys), x0 = (int)floorf(xs);
    int y1 = min(y0 + 1, 71), x1 = min(x0 + 1, 71);
    float wy = ys - (float)y0, wx = xs - (float)x0;

    float a = src[y0 * 72 + x0], b = src[y0 * 72 + x1];
    float c = src[y1 * 72 + x0], d = src[y1 * 72 + x1];
    out[idx] = (a * (1.f - wy) * (1.f - wx) + b * (1.f - wy) * wx
              + c * wy * (1.f - wx)         + d * wy * wx) * inv;
}

extern "C" void kernel_launch(void* const* d_in, const int* in_sizes, int n_in,
                              void* d_out, int out_size) {
    const float* x = (const float*)d_in[0];   // (2,72,72,256) fp32
    cudaFuncSetAttribute(simcam_gemm, cudaFuncAttributeMaxDynamicSharedMemorySize, DYN_SMEM);

    simcam_init<<<(8192 + 255) / 256, 256>>>();
    simcam_conv<<<(2 * MDIM * 128 + 255) / 256, 256>>>(x);
    dim3 grid(NBLK, NBLK);
    simcam_gemm<<<grid, 256, DYN_SMEM>>>();
    simcam_resize<<<(out_size + 255) / 256, 256>>>((float*)d_out, out_size);
}